// round 2
// baseline (speedup 1.0000x reference)
#include <cuda_runtime.h>
#include <math.h>

#define NMAX 50
#define RED_BLOCKS 1184
#define RED_THREADS 256

// Scratch (no allocations allowed in kernel_launch)
static __device__ double g_partials[RED_BLOCKS];
static __device__ float4 g_coef[NMAX + 1];

// ---------------------------------------------------------------------------
// Kernel A: deterministic partial sums of x_i = fl32(fl32(pi_f*d)/lambda_f)
// accumulated in f64.
// ---------------------------------------------------------------------------
__global__ void __launch_bounds__(RED_THREADS) mie_reduce(
    const float* __restrict__ d, int N)
{
    __shared__ double sh[RED_THREADS];
    double s = 0.0;
    const int stride = RED_THREADS * gridDim.x;
    for (int i = blockIdx.x * RED_THREADS + threadIdx.x; i < N; i += stride) {
        // emulate f32 elementwise: (pi32 * d) / lambda32, no FMA, IEEE rounding
        float xi = __fdiv_rn(__fmul_rn(3.14159274101257324f, __ldg(d + i)),
                             5.5e-07f);
        s += (double)xi;
    }
    sh[threadIdx.x] = s;
    __syncthreads();
    for (int o = RED_THREADS / 2; o > 0; o >>= 1) {
        if (threadIdx.x < o) sh[threadIdx.x] += sh[threadIdx.x + o];
        __syncthreads();
    }
    if (threadIdx.x == 0) g_partials[blockIdx.x] = sh[0];
}

// ---------------------------------------------------------------------------
// Kernel B: final deterministic reduce -> x_mean (f32), then Mie a_n, b_n in
// f64 following the reference recurrences exactly. Emits per-n float4:
// (c*a_re, c*a_im, c*b_re, c*b_im) with c = (2n+1)/(n(n+1)).
// ---------------------------------------------------------------------------
__global__ void mie_coeffs(int nPartials, int N)
{
    __shared__ double sh[256];
    double s = 0.0;
    for (int i = threadIdx.x; i < nPartials; i += 256) s += g_partials[i];
    sh[threadIdx.x] = s;
    __syncthreads();
    for (int o = 128; o > 0; o >>= 1) {
        if (threadIdx.x < o) sh[threadIdx.x] += sh[threadIdx.x + o];
        __syncthreads();
    }
    if (threadIdx.x != 0) return;

    const float  xf  = (float)(sh[0] / (double)N);  // f32 x_mean, correctly rounded
    const double x   = (double)xf;
    const float  mxf = 1.31f * xf;                  // f32 m*x as in reference
    const double mx  = (double)mxf;
    const double m   = (double)1.31f;               // f32(1.31) widened

    double jx[NMAX + 1], yx[NMAX + 1], jm[NMAX + 1];
    {
        double sx = sin(x), cx = cos(x);
        jx[0] = sx / x;
        jx[1] = sx / (x * x) - cx / x;
        yx[0] = -cx / x;
        yx[1] = -cx / (x * x) - sx / x;
        for (int n = 1; n < NMAX; n++) {
            double c = (2.0 * n + 1.0) / x;
            jx[n + 1] = c * jx[n] - jx[n - 1];
            yx[n + 1] = c * yx[n] - yx[n - 1];
        }
        double sm = sin(mx), cm = cos(mx);
        jm[0] = sm / mx;
        jm[1] = sm / (mx * mx) - cm / mx;
        for (int n = 1; n < NMAX; n++) {
            double c = (2.0 * n + 1.0) / mx;
            jm[n + 1] = c * jm[n] - jm[n - 1];
        }
    }

    for (int n = 1; n <= NMAX; n++) {
        double nn  = (double)n;
        double dj  = jm[n - 1] - (nn + 1.0) / mx * jm[n];
        double D   = dj / (jm[n] + 1e-10);
        double psi  = x * jx[n];
        double psi1 = x * jx[n - 1];
        double xire  = x * jx[n],     xiim  = x * yx[n];
        double xi1re = x * jx[n - 1], xi1im = x * yx[n - 1];
        double fa = D / m + nn / x;
        double fb = m * D + nn / x;

        // a = (fa*psi - psi1) / (fa*xi - xi1 + EPS)   (EPS on real part)
        double numa = fa * psi - psi1;
        double dre  = fa * xire - xi1re + 1e-10;
        double dim  = fa * xiim - xi1im;
        double den  = dre * dre + dim * dim;
        double are  =  numa * dre / den;
        double aim  = -numa * dim / den;

        double numb = fb * psi - psi1;
        double ebre = fb * xire - xi1re + 1e-10;
        double ebim = fb * xiim - xi1im;
        double denb = ebre * ebre + ebim * ebim;
        double bre  =  numb * ebre / denb;
        double bim  = -numb * ebim / denb;

        double c = (2.0 * nn + 1.0) / (nn * (nn + 1.0));
        g_coef[n] = make_float4((float)(c * are), (float)(c * aim),
                                (float)(c * bre), (float)(c * bim));
    }
}

// ---------------------------------------------------------------------------
// Kernel C: per-element angular sum. Fully unrolled n-loop, coefficient table
// in shared memory, recurrence multipliers as compile-time immediates.
// ---------------------------------------------------------------------------
__global__ void __launch_bounds__(256) mie_main(
    const float* __restrict__ theta, float* __restrict__ out, int N)
{
    __shared__ float4 sc[NMAX + 1];
    if (threadIdx.x <= NMAX) sc[threadIdx.x] = g_coef[threadIdx.x];
    __syncthreads();

    int i = blockIdx.x * 256 + threadIdx.x;
    if (i >= N) return;

    float t = __ldg(theta + i);
    float sn, ct;
    sincosf(t, &sn, &ct);
    float st  = sn + 1e-10f;
    float inv = 1.0f / st;

    // P1 = -sqrt(max(1 - ct*ct, 0)) -- NO fma contraction (match reference
    // rounding through the cancellation at small sin(theta))
    float c2  = __fmul_rn(ct, ct);
    float om  = __fadd_rn(1.0f, -c2);
    float P1  = -sqrtf(fmaxf(om, 0.0f));

    // carry q_n = P_n / sin_t
    float qp = 0.0f;
    float qc = P1 * inv;

    // n = 1 (tau_1 = cos_t per reference's where-clause)
    float4 k  = sc[1];
    float pi  = qc;
    float tau = ct;
    float S1r = fmaf(k.x, pi, k.z * tau);
    float S1i = fmaf(k.y, pi, k.w * tau);
    float S2r = fmaf(k.x, tau, k.z * pi);
    float S2i = fmaf(k.y, tau, k.w * pi);
    float u   = ct * qc;
    float qn  = 3.0f * u;      // P_prev = 0 at n=1
    qp = qc; qc = qn;

#pragma unroll
    for (int n = 2; n <= NMAX; n++) {
        const float fn  = (float)n;
        const float fn1 = (float)(n + 1);
        const float rA  = (float)((2.0 * n + 1.0) / (double)n);  // (2n+1)/n
        const float rB  = (float)(((double)n + 1.0) / (double)n); // (n+1)/n

        k  = sc[n];
        u  = ct * qc;
        pi = qc;
        float t1 = fn1 * qp;
        tau = fmaf(fn, u, -t1);

        S1r = fmaf(k.x, pi,  S1r); S1r = fmaf(k.z, tau, S1r);
        S1i = fmaf(k.y, pi,  S1i); S1i = fmaf(k.w, tau, S1i);
        S2r = fmaf(k.x, tau, S2r); S2r = fmaf(k.z, pi,  S2r);
        S2i = fmaf(k.y, tau, S2i); S2i = fmaf(k.w, pi,  S2i);

        float qnn = fmaf(rA, u, -(rB * qp));
        qp = qc; qc = qnn;
    }

    float inten = S1r * S1r + S1i * S1i + S2r * S2r + S2i * S2i;
    // 0.5 * lambda^2 / (4 pi^2), folded in double at compile time
    const float SCALE = (float)(0.5 * (5.5e-7 * 5.5e-7) /
                                (4.0 * 3.14159265358979323846 *
                                       3.14159265358979323846));
    out[i] = inten * SCALE;
}

// ---------------------------------------------------------------------------
extern "C" void kernel_launch(void* const* d_in, const int* in_sizes, int n_in,
                              void* d_out, int out_size)
{
    const float* d     = (const float*)d_in[0];   // particle_diameter
    const float* theta = (const float*)d_in[1];   // scattering_angle
    float*       out   = (float*)d_out;
    int N = in_sizes[0];

    mie_reduce<<<RED_BLOCKS, RED_THREADS>>>(d, N);
    mie_coeffs<<<1, 256>>>(RED_BLOCKS, N);
    int blocks = (N + 255) / 256;
    mie_main<<<blocks, 256>>>(theta, out, N);
}

// round 3
// speedup vs baseline: 1.0776x; 1.0776x over previous
#include <cuda_runtime.h>
#include <math.h>

#define NMAX 50
#define RED_BLOCKS 1184
#define RED_THREADS 256

typedef unsigned long long u64;

// Scratch (no allocations allowed in kernel_launch)
static __device__ double g_partials[RED_BLOCKS];
// Packed per-n table, n=1..50, 8 u64 per n:
// [0]=(n,n) [1]=(-n,-n) [2]=(beta,beta) [3]=(-beta,-beta)
// [4]=(Pr,Pr) [5]=(Pi,Pi) [6]=(Mr,Mr) [7]=(Mi,Mi)
// where P = c*(a+b), M = c*(a-b), c=(2n+1)/(n(n+1)), beta=(n+1)/n
static __device__ u64 g_ptab[NMAX * 8];

// ---------------------------------------------------------------------------
// packed f32x2 helpers (Blackwell dual-rate FP32 path)
// ---------------------------------------------------------------------------
__device__ __forceinline__ u64 pk2(float lo, float hi) {
    u64 r; asm("mov.b64 %0, {%1, %2};" : "=l"(r) : "f"(lo), "f"(hi)); return r;
}
__device__ __forceinline__ void unpk2(float& lo, float& hi, u64 v) {
    asm("mov.b64 {%0, %1}, %2;" : "=f"(lo), "=f"(hi) : "l"(v));
}
__device__ __forceinline__ u64 fma2(u64 a, u64 b, u64 c) {
    u64 d; asm("fma.rn.f32x2 %0, %1, %2, %3;" : "=l"(d) : "l"(a), "l"(b), "l"(c));
    return d;
}
__device__ __forceinline__ u64 mul2(u64 a, u64 b) {
    u64 d; asm("mul.rn.f32x2 %0, %1, %2;" : "=l"(d) : "l"(a), "l"(b));
    return d;
}
__device__ __forceinline__ u64 add2(u64 a, u64 b) {
    u64 d; asm("add.rn.f32x2 %0, %1, %2;" : "=l"(d) : "l"(a), "l"(b));
    return d;
}

// ---------------------------------------------------------------------------
// Kernel A: f64 partial sums of raw d (pi/lambda applied once at the end;
// per-element f32 rounding noise averages out: ~1e-4 ulp effect on x_mean).
// ---------------------------------------------------------------------------
__global__ void __launch_bounds__(RED_THREADS) mie_reduce(
    const float* __restrict__ d, int N)
{
    __shared__ double sh[RED_THREADS];
    const float4* d4 = (const float4*)d;
    const int N4 = N >> 2;
    double s = 0.0;
    const int stride = RED_THREADS * gridDim.x;
    for (int i = blockIdx.x * RED_THREADS + threadIdx.x; i < N4; i += stride) {
        float4 v = __ldg(d4 + i);
        s += (double)v.x + (double)v.y + (double)v.z + (double)v.w;
    }
    if (blockIdx.x == 0 && threadIdx.x == 0)       // tail (deterministic)
        for (int i = N4 << 2; i < N; i++) s += (double)__ldg(d + i);
    sh[threadIdx.x] = s;
    __syncthreads();
    for (int o = RED_THREADS / 2; o > 0; o >>= 1) {
        if (threadIdx.x < o) sh[threadIdx.x] += sh[threadIdx.x + o];
        __syncthreads();
    }
    if (threadIdx.x == 0) g_partials[blockIdx.x] = sh[0];
}

// ---------------------------------------------------------------------------
// Kernel B: final reduce -> x_mean (f32), f64 Mie recurrences, emit packed
// per-n constant table.
// ---------------------------------------------------------------------------
__global__ void mie_coeffs(int nPartials, int N)
{
    __shared__ double sh[256];
    double s = 0.0;
    for (int i = threadIdx.x; i < nPartials; i += 256) s += g_partials[i];
    sh[threadIdx.x] = s;
    __syncthreads();
    for (int o = 128; o > 0; o >>= 1) {
        if (threadIdx.x < o) sh[threadIdx.x] += sh[threadIdx.x + o];
        __syncthreads();
    }
    if (threadIdx.x != 0) return;

    const double PI_WF  = (double)3.14159274101257324f;  // f32 pi, widened
    const double LAM_WF = (double)5.5e-07f;              // f32 lambda, widened
    const float  xf  = (float)(PI_WF * (sh[0] / (double)N) / LAM_WF);
    const double x   = (double)xf;
    const float  mxf = 1.31f * xf;                       // f32 m*x as in ref
    const double mx  = (double)mxf;
    const double m   = (double)1.31f;

    double jx[NMAX + 1], yx[NMAX + 1], jm[NMAX + 1];
    {
        double sx = sin(x), cx = cos(x);
        jx[0] = sx / x;
        jx[1] = sx / (x * x) - cx / x;
        yx[0] = -cx / x;
        yx[1] = -cx / (x * x) - sx / x;
        for (int n = 1; n < NMAX; n++) {
            double c = (2.0 * n + 1.0) / x;
            jx[n + 1] = c * jx[n] - jx[n - 1];
            yx[n + 1] = c * yx[n] - yx[n - 1];
        }
        double sm = sin(mx), cm = cos(mx);
        jm[0] = sm / mx;
        jm[1] = sm / (mx * mx) - cm / mx;
        for (int n = 1; n < NMAX; n++) {
            double c = (2.0 * n + 1.0) / mx;
            jm[n + 1] = c * jm[n] - jm[n - 1];
        }
    }

    for (int n = 1; n <= NMAX; n++) {
        double nn  = (double)n;
        double dj  = jm[n - 1] - (nn + 1.0) / mx * jm[n];
        double D   = dj / (jm[n] + 1e-10);
        double psi  = x * jx[n];
        double psi1 = x * jx[n - 1];
        double xire  = x * jx[n],     xiim  = x * yx[n];
        double xi1re = x * jx[n - 1], xi1im = x * yx[n - 1];
        double fa = D / m + nn / x;
        double fb = m * D + nn / x;

        double numa = fa * psi - psi1;
        double dre  = fa * xire - xi1re + 1e-10;
        double dim  = fa * xiim - xi1im;
        double den  = dre * dre + dim * dim;
        double are  =  numa * dre / den;
        double aim  = -numa * dim / den;

        double numb = fb * psi - psi1;
        double ebre = fb * xire - xi1re + 1e-10;
        double ebim = fb * xiim - xi1im;
        double denb = ebre * ebre + ebim * ebim;
        double bre  =  numb * ebre / denb;
        double bim  = -numb * ebim / denb;

        double c = (2.0 * nn + 1.0) / (nn * (nn + 1.0));
        double Ar = c * are, Ai = c * aim, Br = c * bre, Bi = c * bim;

        float Pr  = (float)(Ar + Br), Pi_ = (float)(Ai + Bi);
        float Mr  = (float)(Ar - Br), Mi  = (float)(Ai - Bi);
        float fn  = (float)nn;
        float bet = (float)((nn + 1.0) / nn);

        u64* rec = &g_ptab[(n - 1) * 8];
        #define DUP(v) (((u64)__float_as_uint(v) << 32) | (u64)__float_as_uint(v))
        rec[0] = DUP(fn);   rec[1] = DUP(-fn);
        rec[2] = DUP(bet);  rec[3] = DUP(-bet);
        rec[4] = DUP(Pr);   rec[5] = DUP(Pi_);
        rec[6] = DUP(Mr);   rec[7] = DUP(Mi);
        #undef DUP
    }
}

// ---------------------------------------------------------------------------
// Kernel C: 2 elements per thread, everything in packed f32x2.
// Carries q_n = P_n/sin, t' = u - beta*qp; tau = n*t'; q_{n+1} = t' + beta*u.
// Accumulates T1=S1+S2 via (A+B)(pi+tau), T2=S1-S2 via (A-B)(pi-tau).
// ---------------------------------------------------------------------------
__global__ void __launch_bounds__(256) mie_main(
    const float* __restrict__ theta, float* __restrict__ out, int N)
{
    __shared__ __align__(16) u64 tab[NMAX * 8];
    for (int idx = threadIdx.x; idx < NMAX * 8; idx += 256)
        tab[idx] = g_ptab[idx];
    __syncthreads();

    const int i2 = blockIdx.x * 256 + threadIdx.x;
    const int j0 = i2 * 2;
    if (j0 >= N) return;

    float t0, t1;
    if (j0 + 1 < N) {
        float2 tt = *(const float2*)(theta + j0);
        t0 = tt.x; t1 = tt.y;
    } else {
        t0 = __ldg(theta + j0); t1 = t0;
    }

    // scalar prologue per element
    float sn0, ct0, sn1, ct1;
    sincosf(t0, &sn0, &ct0);
    sincosf(t1, &sn1, &ct1);
    float inv0 = 1.0f / (sn0 + 1e-10f);
    float inv1 = 1.0f / (sn1 + 1e-10f);
    // P1 = -sqrt(max(1-ct^2,0)), no FMA contraction (match ref rounding)
    float om0 = __fadd_rn(1.0f, -__fmul_rn(ct0, ct0));
    float om1 = __fadd_rn(1.0f, -__fmul_rn(ct1, ct1));
    float pi0 = -sqrtf(fmaxf(om0, 0.0f)) * inv0;
    float pi1 = -sqrtf(fmaxf(om1, 0.0f)) * inv1;

    u64 ct2 = pk2(ct0, ct1);
    u64 qc  = pk2(pi0, pi1);     // q_1 = P_1/sin

    // n = 1 peeled: tau = ct (reference's where clause)
    u64 T1r, T1i, T2r, T2i;
    {
        const u64* rec = &tab[0];          // n=1 record
        u64 p = add2(qc, ct2);             // pi + tau
        u64 mneg = pk2(-ct0, -ct1);
        u64 mm = add2(qc, mneg);           // pi - tau
        T1r = mul2(rec[4], p);
        T1i = mul2(rec[5], p);
        T2r = mul2(rec[6], mm);
        T2i = mul2(rec[7], mm);
    }
    // q_2 = 3*ct*q_1 (q_0 = 0)
    u64 u  = mul2(ct2, qc);
    u64 qp = qc;
    qc = mul2(pk2(3.0f, 3.0f), u);

#pragma unroll
    for (int n = 2; n <= NMAX; n++) {
        const u64* rec = &tab[(n - 1) * 8];
        // 16B vector loads of the packed constant pairs
        ulonglong2 cN = *(const ulonglong2*)(rec + 0);  // ( n, -n )
        ulonglong2 cB = *(const ulonglong2*)(rec + 2);  // ( b, -b )
        ulonglong2 cP = *(const ulonglong2*)(rec + 4);  // ( Pr, Pi )
        ulonglong2 cM = *(const ulonglong2*)(rec + 6);  // ( Mr, Mi )

        u        = mul2(ct2, qc);          // u = ct*q_n
        u64 tp   = fma2(cB.y, qp, u);      // t' = u - beta*q_{n-1}
        u64 qn   = fma2(cB.x, u, tp);      // q_{n+1} = t' + beta*u
        u64 p    = fma2(cN.x, tp, qc);     // pi + tau = pi + n*t'
        u64 mm   = fma2(cN.y, tp, qc);     // pi - tau
        T1r = fma2(cP.x, p,  T1r);
        T1i = fma2(cP.y, p,  T1i);
        T2r = fma2(cM.x, mm, T2r);
        T2i = fma2(cM.y, mm, T2i);
        qp = qc; qc = qn;
    }

    // out = (|T1|^2 + |T2|^2) * lambda^2/(16 pi^2)
    const float SCALE = (float)((5.5e-7 * 5.5e-7) /
                                (16.0 * 3.14159265358979323846 *
                                        3.14159265358979323846));
    float a0, a1, b0, b1, c0, c1, d0, d1;
    unpk2(a0, a1, T1r); unpk2(b0, b1, T1i);
    unpk2(c0, c1, T2r); unpk2(d0, d1, T2i);
    float o0 = (a0 * a0 + b0 * b0 + c0 * c0 + d0 * d0) * SCALE;
    float o1 = (a1 * a1 + b1 * b1 + c1 * c1 + d1 * d1) * SCALE;

    if (j0 + 1 < N) {
        *(float2*)(out + j0) = make_float2(o0, o1);
    } else {
        out[j0] = o0;
    }
}

// ---------------------------------------------------------------------------
extern "C" void kernel_launch(void* const* d_in, const int* in_sizes, int n_in,
                              void* d_out, int out_size)
{
    const float* d     = (const float*)d_in[0];   // particle_diameter
    const float* theta = (const float*)d_in[1];   // scattering_angle
    float*       out   = (float*)d_out;
    int N = in_sizes[0];

    mie_reduce<<<RED_BLOCKS, RED_THREADS>>>(d, N);
    mie_coeffs<<<1, 256>>>(RED_BLOCKS, N);
    int pairs  = (N + 1) / 2;
    int blocks = (pairs + 255) / 256;
    mie_main<<<blocks, 256>>>(theta, out, N);
}